// round 2
// baseline (speedup 1.0000x reference)
#include <cuda_runtime.h>
#include <math.h>

// ---------------- scratch (device globals; no allocations allowed) -----------
__device__ float g_Xq[4096 * 1536];       // X @ Wq_down^T
__device__ float g_Qb[4096 * 2048];       // Xq @ Wq_up^T   (layout [row][h*128+d])
__device__ float g_Cb[4096 * 512];        // X @ Wkv_down^T
__device__ float g_Kb[16 * 4096 * 128];   // [h][row][d]
__device__ float g_Vb[16 * 4096 * 128];   // [h][row][d]
__device__ float g_AO[4096 * 2048];       // attention output [row][h*128+d]

// ---------------- generic tiled SGEMM ---------------------------------------
// C[M,N] = A[M,K] @ op(B),  BT=true: B is [N,K] row-major (C += A*B^T)
//                           BT=false: B is [K,N] row-major (C += A*B)
// Tile 128x128x16, 256 threads, 8x8 microtile. All dims assumed divisible.
template <bool BT>
__global__ __launch_bounds__(256)
void gemm_kernel(const float* __restrict__ A, const float* __restrict__ B,
                 float* __restrict__ C,
                 int M, int N, int K, int lda, int ldb, int ldc,
                 int bStrideZ, int cStrideZ)
{
    B += (long)blockIdx.z * bStrideZ;
    C += (long)blockIdx.z * cStrideZ;

    __shared__ float As[16][132];   // A tile transposed: As[k][m]
    __shared__ float Bs[16][132];   // B tile: Bs[k][n]

    const int tid = threadIdx.x;
    const int tx  = tid & 15;       // column group
    const int ty  = tid >> 4;       // row group
    const int mBase = blockIdx.y * 128;
    const int nBase = blockIdx.x * 128;

    float acc[8][8];
#pragma unroll
    for (int i = 0; i < 8; i++)
#pragma unroll
        for (int j = 0; j < 8; j++) acc[i][j] = 0.f;

    const int loRow = tid >> 1;          // 0..127
    const int loK   = (tid & 1) * 8;     // 0 or 8

    for (int kt = 0; kt < K; kt += 16) {
        // ---- load A tile (transpose into As[k][m]) ----
        {
            const float* ap = A + (long)(mBase + loRow) * lda + kt + loK;
            float4 a0 = *(const float4*)(ap);
            float4 a1 = *(const float4*)(ap + 4);
            float av[8] = {a0.x, a0.y, a0.z, a0.w, a1.x, a1.y, a1.z, a1.w};
#pragma unroll
            for (int u = 0; u < 8; u++) As[loK + u][loRow] = av[u];
        }
        // ---- load B tile into Bs[k][n] ----
        if (BT) {
            const float* bp = B + (long)(nBase + loRow) * ldb + kt + loK;
            float4 b0 = *(const float4*)(bp);
            float4 b1 = *(const float4*)(bp + 4);
            float bv[8] = {b0.x, b0.y, b0.z, b0.w, b1.x, b1.y, b1.z, b1.w};
#pragma unroll
            for (int u = 0; u < 8; u++) Bs[loK + u][loRow] = bv[u];
        } else {
            const int bk = tid >> 4;          // 0..15
            const int bn = (tid & 15) * 8;    // 0..120
            const float* bp = B + (long)(kt + bk) * ldb + nBase + bn;
            float4 b0 = *(const float4*)(bp);
            float4 b1 = *(const float4*)(bp + 4);
            *(float4*)&Bs[bk][bn]     = b0;
            *(float4*)&Bs[bk][bn + 4] = b1;
        }
        __syncthreads();

#pragma unroll
        for (int kk = 0; kk < 16; kk++) {
            float a[8], b[8];
            float4 av0 = *(const float4*)&As[kk][ty * 8];
            float4 av1 = *(const float4*)&As[kk][ty * 8 + 4];
            a[0] = av0.x; a[1] = av0.y; a[2] = av0.z; a[3] = av0.w;
            a[4] = av1.x; a[5] = av1.y; a[6] = av1.z; a[7] = av1.w;
#pragma unroll
            for (int j = 0; j < 8; j++) b[j] = Bs[kk][tx + 16 * j];
#pragma unroll
            for (int i = 0; i < 8; i++)
#pragma unroll
                for (int j = 0; j < 8; j++) acc[i][j] = fmaf(a[i], b[j], acc[i][j]);
        }
        __syncthreads();
    }

#pragma unroll
    for (int i = 0; i < 8; i++) {
        const int row = mBase + ty * 8 + i;
#pragma unroll
        for (int j = 0; j < 8; j++)
            C[(long)row * ldc + nBase + tx + 16 * j] = acc[i][j];
    }
}

// ---------------- flash attention (fp32, causal + ALiBi) ---------------------
// grid: (L/64, H, B); block 256 (16x16). Br=Bc=64, d=128.
// Q layout [row=b*L+s][h*128+d]; K/V layout [h][row][d]; AO like Q.
#define QT_STRIDE 65
#define VS_STRIDE 132
#define PS_STRIDE 68
#define SCALE_F 0.08838834764831845f   // 1/sqrt(128)

__global__ __launch_bounds__(256)
void flash_kernel(const float* __restrict__ Q, const float* __restrict__ Kb,
                  const float* __restrict__ Vb, float* __restrict__ AO)
{
    extern __shared__ float sm[];
    float* Qt = sm;                          // [128][65]  (k-major)
    float* Kt = Qt + 128 * QT_STRIDE;        // [128][65]  (k-major)
    float* Vs = Kt + 128 * QT_STRIDE;        // [64][132]  (row-major)
    float* Ps = Vs + 64 * VS_STRIDE;         // [64][68]

    const int qt = blockIdx.x;
    const int h  = blockIdx.y;
    const int b  = blockIdx.z;
    const int tid = threadIdx.x;
    const int tx = tid & 15;
    const int ty = tid >> 4;

    const int rowBase = b * 2048 + qt * 64;  // global row into Q/AO
    const float slope = exp2f(-0.5f * (float)(h + 1));

    // ---- stage Q tile transposed ----
    {
        const int r  = tid >> 2;             // 0..63
        const int c0 = (tid & 3) * 32;       // 0,32,64,96
        const float* qp = Q + (long)(rowBase + r) * 2048 + h * 128 + c0;
#pragma unroll
        for (int u = 0; u < 8; u++) {
            float4 v = *(const float4*)(qp + u * 4);
            const int c = c0 + u * 4;
            Qt[(c + 0) * QT_STRIDE + r] = v.x;
            Qt[(c + 1) * QT_STRIDE + r] = v.y;
            Qt[(c + 2) * QT_STRIDE + r] = v.z;
            Qt[(c + 3) * QT_STRIDE + r] = v.w;
        }
    }

    float m[4], l[4], o[4][8];
#pragma unroll
    for (int i = 0; i < 4; i++) {
        m[i] = -1e30f; l[i] = 0.f;
#pragma unroll
        for (int c = 0; c < 8; c++) o[i][c] = 0.f;
    }

    const float* Kh = Kb + ((long)h * 4096 + b * 2048) * 128;
    const float* Vh = Vb + ((long)h * 4096 + b * 2048) * 128;

    __syncthreads();

    for (int jt = 0; jt <= qt; jt++) {
        // ---- stage K (transposed) and V (row-major) tiles ----
        {
            const int r  = tid >> 2;
            const int c0 = (tid & 3) * 32;
            const float* kp = Kh + (long)(jt * 64 + r) * 128 + c0;
            const float* vp = Vh + (long)(jt * 64 + r) * 128 + c0;
#pragma unroll
            for (int u = 0; u < 8; u++) {
                float4 kv = *(const float4*)(kp + u * 4);
                const int c = c0 + u * 4;
                Kt[(c + 0) * QT_STRIDE + r] = kv.x;
                Kt[(c + 1) * QT_STRIDE + r] = kv.y;
                Kt[(c + 2) * QT_STRIDE + r] = kv.z;
                Kt[(c + 3) * QT_STRIDE + r] = kv.w;
                float4 vv = *(const float4*)(vp + u * 4);
                *(float4*)&Vs[r * VS_STRIDE + c] = vv;
            }
        }
        __syncthreads();

        // ---- S = Q K^T ----
        float s[4][4];
#pragma unroll
        for (int i = 0; i < 4; i++)
#pragma unroll
            for (int j = 0; j < 4; j++) s[i][j] = 0.f;

#pragma unroll 4
        for (int kk = 0; kk < 128; kk++) {
            float qv[4], kv[4];
#pragma unroll
            for (int i = 0; i < 4; i++) qv[i] = Qt[kk * QT_STRIDE + ty * 4 + i];
#pragma unroll
            for (int j = 0; j < 4; j++) kv[j] = Kt[kk * QT_STRIDE + tx + 16 * j];
#pragma unroll
            for (int i = 0; i < 4; i++)
#pragma unroll
                for (int j = 0; j < 4; j++) s[i][j] = fmaf(qv[i], kv[j], s[i][j]);
        }

        // ---- scale + ALiBi + causal mask ----
#pragma unroll
        for (int i = 0; i < 4; i++) {
            const int grow = qt * 64 + ty * 4 + i;
#pragma unroll
            for (int j = 0; j < 4; j++) {
                const int gcol = jt * 64 + tx + 16 * j;
                if (gcol > grow) s[i][j] = -1e30f;
                else s[i][j] = s[i][j] * SCALE_F - slope * (float)(grow - gcol);
            }
        }

        // ---- online softmax ----
        float mn[4];
#pragma unroll
        for (int i = 0; i < 4; i++) {
            float v = fmaxf(fmaxf(s[i][0], s[i][1]), fmaxf(s[i][2], s[i][3]));
            v = fmaxf(v, __shfl_xor_sync(0xffffffffu, v, 1));
            v = fmaxf(v, __shfl_xor_sync(0xffffffffu, v, 2));
            v = fmaxf(v, __shfl_xor_sync(0xffffffffu, v, 4));
            v = fmaxf(v, __shfl_xor_sync(0xffffffffu, v, 8));
            mn[i] = v;
        }

        float rs[4];
#pragma unroll
        for (int i = 0; i < 4; i++) {
            const float mi = fmaxf(m[i], mn[i]);
            const float alpha = __expf(m[i] - mi);
            float acc = 0.f;
#pragma unroll
            for (int j = 0; j < 4; j++) {
                float p = __expf(s[i][j] - mi);
                acc += p;
                Ps[(ty * 4 + i) * PS_STRIDE + tx + 16 * j] = p;
            }
            acc += __shfl_xor_sync(0xffffffffu, acc, 1);
            acc += __shfl_xor_sync(0xffffffffu, acc, 2);
            acc += __shfl_xor_sync(0xffffffffu, acc, 4);
            acc += __shfl_xor_sync(0xffffffffu, acc, 8);
            rs[i] = acc;
            l[i] = l[i] * alpha + acc;
            m[i] = mi;
#pragma unroll
            for (int c = 0; c < 8; c++) o[i][c] *= alpha;
        }
        __syncthreads();

        // ---- O += P V ----
#pragma unroll 2
        for (int kc = 0; kc < 64; kc++) {
            float pv[4], vv[8];
#pragma unroll
            for (int i = 0; i < 4; i++) pv[i] = Ps[(ty * 4 + i) * PS_STRIDE + kc];
#pragma unroll
            for (int c = 0; c < 8; c++) vv[c] = Vs[kc * VS_STRIDE + tx + 16 * c];
#pragma unroll
            for (int i = 0; i < 4; i++)
#pragma unroll
                for (int c = 0; c < 8; c++) o[i][c] = fmaf(pv[i], vv[c], o[i][c]);
        }
        __syncthreads();
    }

    // ---- normalize + write ----
#pragma unroll
    for (int i = 0; i < 4; i++) {
        const float inv = 1.f / l[i];
        const long row = rowBase + ty * 4 + i;
#pragma unroll
        for (int c = 0; c < 8; c++)
            AO[row * 2048 + h * 128 + tx + 16 * c] = o[i][c] * inv;
    }
}

// ---------------- launch ------------------------------------------------------
extern "C" void kernel_launch(void* const* d_in, const int* in_sizes, int n_in,
                              void* d_out, int out_size)
{
    const float* X    = (const float*)d_in[0];  // [2,2048,2048]
    const float* Wqd  = (const float*)d_in[1];  // [1536,2048]
    const float* Wqu  = (const float*)d_in[2];  // [2048,1536]
    const float* Wkvd = (const float*)d_in[3];  // [512,2048]
    const float* kup  = (const float*)d_in[4];  // [16,512,128]
    const float* vup  = (const float*)d_in[5];  // [16,512,128]
    const float* Wo   = (const float*)d_in[6];  // [2048,2048]
    float* out = (float*)d_out;                 // [2,2048,2048]

    float *Xq, *Qb, *Cb, *Kb, *Vb, *AO;
    cudaGetSymbolAddress((void**)&Xq, g_Xq);
    cudaGetSymbolAddress((void**)&Qb, g_Qb);
    cudaGetSymbolAddress((void**)&Cb, g_Cb);
    cudaGetSymbolAddress((void**)&Kb, g_Kb);
    cudaGetSymbolAddress((void**)&Vb, g_Vb);
    cudaGetSymbolAddress((void**)&AO, g_AO);

    const size_t smem = (size_t)(128 * QT_STRIDE * 2 + 64 * VS_STRIDE + 64 * PS_STRIDE)
                        * sizeof(float);   // ~115 KB
    cudaFuncSetAttribute(flash_kernel, cudaFuncAttributeMaxDynamicSharedMemorySize,
                         (int)smem);

    // 1) Xq = X @ Wq_down^T              [4096,1536] = [4096,2048]@[1536,2048]^T
    gemm_kernel<true><<<dim3(12, 32), 256>>>(X, Wqd, Xq,
        4096, 1536, 2048, 2048, 2048, 1536, 0, 0);
    // 2) Q = Xq @ Wq_up^T                [4096,2048]
    gemm_kernel<true><<<dim3(16, 32), 256>>>(Xq, Wqu, Qb,
        4096, 2048, 1536, 1536, 1536, 2048, 0, 0);
    // 3) C = X @ Wkv_down^T              [4096,512]
    gemm_kernel<true><<<dim3(4, 32), 256>>>(X, Wkvd, Cb,
        4096, 512, 2048, 2048, 2048, 512, 0, 0);
    // 4) K[h] = C @ k_up[h]              16 x ([4096,128] = [4096,512]@[512,128])
    gemm_kernel<false><<<dim3(1, 32, 16), 256>>>(Cb, kup, Kb,
        4096, 128, 512, 512, 128, 128, 512 * 128, 4096 * 128);
    // 5) V[h] = C @ v_up[h]
    gemm_kernel<false><<<dim3(1, 32, 16), 256>>>(Cb, vup, Vb,
        4096, 128, 512, 512, 128, 128, 512 * 128, 4096 * 128);
    // 6) attention
    flash_kernel<<<dim3(32, 16, 2), 256, smem>>>(Qb, Kb, Vb, AO);
    // 7) out = AO @ Wo^T                 [4096,2048]
    gemm_kernel<true><<<dim3(16, 32), 256>>>(AO, Wo, out,
        4096, 2048, 2048, 2048, 2048, 2048, 0, 0);
}

// round 3
// speedup vs baseline: 1.5703x; 1.5703x over previous
#include <cuda_runtime.h>
#include <cuda_bf16.h>
#include <math.h>
#include <stdint.h>

// ---------------- scratch (device globals; no allocations allowed) -----------
__device__ float g_Xq[4096 * 1536];       // X @ Wq_down^T
__device__ float g_Qb[4096 * 2048];       // Xq @ Wq_up^T   (layout [row][h*128+d])
__device__ float g_Cb[4096 * 512];        // X @ Wkv_down^T
__device__ float g_Kb[16 * 4096 * 128];   // [h][row][d]
__device__ float g_Vb[16 * 4096 * 128];   // [h][row][d]
__device__ float g_AO[4096 * 2048];       // attention output [row][h*128+d]

// bf16 hi/lo planes of the weights ([N][K] layout; kup/vup transposed)
__device__ __nv_bfloat16 g_Wqd_hi[1536 * 2048], g_Wqd_lo[1536 * 2048];
__device__ __nv_bfloat16 g_Wqu_hi[2048 * 1536], g_Wqu_lo[2048 * 1536];
__device__ __nv_bfloat16 g_Wkvd_hi[512 * 2048], g_Wkvd_lo[512 * 2048];
__device__ __nv_bfloat16 g_Wo_hi[2048 * 2048], g_Wo_lo[2048 * 2048];
__device__ __nv_bfloat16 g_kupT_hi[16 * 128 * 512], g_kupT_lo[16 * 128 * 512];
__device__ __nv_bfloat16 g_vupT_hi[16 * 128 * 512], g_vupT_lo[16 * 128 * 512];

// ---------------- weight prep: fp32 -> bf16 hi/lo planes ---------------------
__global__ void conv_plain(const float* __restrict__ in, __nv_bfloat16* __restrict__ hi,
                           __nv_bfloat16* __restrict__ lo, int n)
{
    int i = blockIdx.x * blockDim.x + threadIdx.x;
    if (i >= n) return;
    float x = in[i];
    __nv_bfloat16 h = __float2bfloat16(x);
    hi[i] = h;
    lo[i] = __float2bfloat16(x - __bfloat162float(h));
}

// in: [Z][K][N] fp32 -> out planes [Z][N][K]
__global__ void conv_transpose(const float* __restrict__ in, __nv_bfloat16* __restrict__ hi,
                               __nv_bfloat16* __restrict__ lo, int Z, int K, int N)
{
    long i = (long)blockIdx.x * blockDim.x + threadIdx.x;
    long total = (long)Z * K * N;
    if (i >= total) return;
    int n = (int)(i % N);
    long t = i / N;
    int k = (int)(t % K);
    int z = (int)(t / K);
    float x = in[i];
    __nv_bfloat16 h = __float2bfloat16(x);
    long o = ((long)z * N + n) * K + k;
    hi[o] = h;
    lo[o] = __float2bfloat16(x - __bfloat162float(h));
}

// ---------------- bf16x3 tensor-core GEMM ------------------------------------
// C[M,N] = A[M,K] (fp32) @ B^T where B given as bf16 hi/lo planes in [N][K].
// CTA tile 128x128x32, 8 warps (2x4), warp tile 64x32, mma.m16n8k16.bf16.
#define BM 128
#define BN 128
#define BK 32
#define LDSS 40                     // smem row stride in bf16 elems (80B -> conflict-free ldmatrix)
#define TILE_ELE (128 * LDSS)       // elems per plane
#define GEMM_SMEM (2 * 4 * TILE_ELE * 2)  // bytes: 2 stages x 4 planes

__device__ __forceinline__ uint32_t su(const void* p) {
    return (uint32_t)__cvta_generic_to_shared(p);
}

__device__ __forceinline__ void ldsm4(uint32_t* r, uint32_t addr) {
    asm volatile("ldmatrix.sync.aligned.m8n8.x4.shared.b16 {%0,%1,%2,%3}, [%4];"
                 : "=r"(r[0]), "=r"(r[1]), "=r"(r[2]), "=r"(r[3]) : "r"(addr));
}

__device__ __forceinline__ void mma16816(float* c, const uint32_t* a, const uint32_t* b) {
    asm volatile("mma.sync.aligned.m16n8k16.row.col.f32.bf16.bf16.f32 "
                 "{%0,%1,%2,%3}, {%4,%5,%6,%7}, {%8,%9}, {%0,%1,%2,%3};"
                 : "+f"(c[0]), "+f"(c[1]), "+f"(c[2]), "+f"(c[3])
                 : "r"(a[0]), "r"(a[1]), "r"(a[2]), "r"(a[3]), "r"(b[0]), "r"(b[1]));
}

struct StageRegs {
    float4 a[4];
    uint4 bh[2];
    uint4 bl[2];
};

__global__ __launch_bounds__(256)
void gemm_tc(const float* __restrict__ A,
             const __nv_bfloat16* __restrict__ Bhi,
             const __nv_bfloat16* __restrict__ Blo,
             float* __restrict__ C,
             int M, int N, int K, int lda, int ldc,
             long bStrideZ, long cStrideZ)
{
    extern __shared__ __nv_bfloat16 smem[];

    const int tid = threadIdx.x;
    const int z = blockIdx.z;
    const int mBase = blockIdx.y * BM;
    const int nBase = blockIdx.x * BN;

    const __nv_bfloat16* BhiZ = Bhi + z * bStrideZ;
    const __nv_bfloat16* BloZ = Blo + z * bStrideZ;
    float* Cz = C + z * cStrideZ;

    // ---- cooperative load mapping ----
    const int ldRow = tid >> 1;          // 0..127
    const int ldCol = (tid & 1) * 16;    // 0 or 16
    const int stsOff = ldRow * LDSS + ldCol;

    // ---- fragment (ldmatrix) address components ----
    const int lane = tid & 31;
    const int wid = tid >> 5;
    const int wm = wid >> 2;             // 0..1  (64-row slab)
    const int wn = wid & 3;              // 0..3  (32-col slab)
    const int aRowL = wm * 64 + (lane & 15);
    const int aKL = ((lane >> 4) << 3);
    const int bRowL = wn * 32 + ((lane >> 4) << 3) + (lane & 7);
    const int bKL = ((lane >> 3) & 1) << 3;

    const uint32_t smemBase = su(smem);
    const uint32_t planeBytes = TILE_ELE * 2;

    float acc[4][4][4];
#pragma unroll
    for (int i = 0; i < 4; i++)
#pragma unroll
        for (int j = 0; j < 4; j++)
#pragma unroll
            for (int k = 0; k < 4; k++) acc[i][j][k] = 0.f;

    StageRegs st;
    const int nt = K / BK;

    // ---- prologue: load tile 0, store to stage 0 ----
    {
        const float* ap = A + (long)(mBase + ldRow) * lda + ldCol;
#pragma unroll
        for (int i = 0; i < 4; i++) st.a[i] = *(const float4*)(ap + i * 4);
        const __nv_bfloat16* bph = BhiZ + (long)(nBase + ldRow) * K + ldCol;
        const __nv_bfloat16* bpl = BloZ + (long)(nBase + ldRow) * K + ldCol;
        st.bh[0] = *(const uint4*)(bph); st.bh[1] = *(const uint4*)(bph + 8);
        st.bl[0] = *(const uint4*)(bpl); st.bl[1] = *(const uint4*)(bpl + 8);
    }
    {
        __nv_bfloat16* dAh = smem + 0 * TILE_ELE;
        __nv_bfloat16* dAl = smem + 1 * TILE_ELE;
        __nv_bfloat16* dBh = smem + 2 * TILE_ELE;
        __nv_bfloat16* dBl = smem + 3 * TILE_ELE;
#pragma unroll
        for (int i = 0; i < 4; i++) {
            float4 v = st.a[i];
            __nv_bfloat16 h0 = __float2bfloat16(v.x), h1 = __float2bfloat16(v.y);
            __nv_bfloat16 h2 = __float2bfloat16(v.z), h3 = __float2bfloat16(v.w);
            __nv_bfloat16 l0 = __float2bfloat16(v.x - __bfloat162float(h0));
            __nv_bfloat16 l1 = __float2bfloat16(v.y - __bfloat162float(h1));
            __nv_bfloat16 l2 = __float2bfloat16(v.z - __bfloat162float(h2));
            __nv_bfloat16 l3 = __float2bfloat16(v.w - __bfloat162float(h3));
            *(__nv_bfloat162*)(dAh + stsOff + i * 4)     = __halves2bfloat162(h0, h1);
            *(__nv_bfloat162*)(dAh + stsOff + i * 4 + 2) = __halves2bfloat162(h2, h3);
            *(__nv_bfloat162*)(dAl + stsOff + i * 4)     = __halves2bfloat162(l0, l1);
            *(__nv_bfloat162*)(dAl + stsOff + i * 4 + 2) = __halves2bfloat162(l2, l3);
        }
        *(uint4*)(dBh + stsOff)     = st.bh[0];
        *(uint4*)(dBh + stsOff + 8) = st.bh[1];
        *(uint4*)(dBl + stsOff)     = st.bl[0];
        *(uint4*)(dBl + stsOff + 8) = st.bl[1];
    }
    __syncthreads();

    for (int kt = 0; kt < nt; kt++) {
        const int cur = kt & 1;
        const bool more = (kt + 1 < nt);

        // prefetch next tile into registers
        if (more) {
            const float* ap = A + (long)(mBase + ldRow) * lda + (kt + 1) * BK + ldCol;
#pragma unroll
            for (int i = 0; i < 4; i++) st.a[i] = *(const float4*)(ap + i * 4);
            const __nv_bfloat16* bph = BhiZ + (long)(nBase + ldRow) * K + (kt + 1) * BK + ldCol;
            const __nv_bfloat16* bpl = BloZ + (long)(nBase + ldRow) * K + (kt + 1) * BK + ldCol;
            st.bh[0] = *(const uint4*)(bph); st.bh[1] = *(const uint4*)(bph + 8);
            st.bl[0] = *(const uint4*)(bpl); st.bl[1] = *(const uint4*)(bpl + 8);
        }

        // ---- compute on stage `cur` ----
        const uint32_t sAh = smemBase + (cur * 4 + 0) * planeBytes;
        const uint32_t sAl = smemBase + (cur * 4 + 1) * planeBytes;
        const uint32_t sBh = smemBase + (cur * 4 + 2) * planeBytes;
        const uint32_t sBl = smemBase + (cur * 4 + 3) * planeBytes;

#pragma unroll
        for (int ks = 0; ks < BK; ks += 16) {
            uint32_t Ah[4][4], Al[4][4];
#pragma unroll
            for (int mb = 0; mb < 4; mb++) {
                const uint32_t off = ((aRowL + mb * 16) * LDSS + aKL + ks) * 2;
                ldsm4(Ah[mb], sAh + off);
                ldsm4(Al[mb], sAl + off);
            }
            uint32_t Bh[4][2], Bl[4][2];
#pragma unroll
            for (int nb2 = 0; nb2 < 2; nb2++) {
                const uint32_t off = ((bRowL + nb2 * 16) * LDSS + bKL + ks) * 2;
                uint32_t r[4];
                ldsm4(r, sBh + off);
                Bh[nb2 * 2][0] = r[0]; Bh[nb2 * 2][1] = r[1];
                Bh[nb2 * 2 + 1][0] = r[2]; Bh[nb2 * 2 + 1][1] = r[3];
                ldsm4(r, sBl + off);
                Bl[nb2 * 2][0] = r[0]; Bl[nb2 * 2][1] = r[1];
                Bl[nb2 * 2 + 1][0] = r[2]; Bl[nb2 * 2 + 1][1] = r[3];
            }
#pragma unroll
            for (int mb = 0; mb < 4; mb++)
#pragma unroll
                for (int nb = 0; nb < 4; nb++) {
                    mma16816(acc[mb][nb], Ah[mb], Bh[nb]);
                    mma16816(acc[mb][nb], Ah[mb], Bl[nb]);
                    mma16816(acc[mb][nb], Al[mb], Bh[nb]);
                }
        }

        // store prefetched tile into the other stage
        if (more) {
            const int nxt = cur ^ 1;
            __nv_bfloat16* dAh = smem + (nxt * 4 + 0) * TILE_ELE;
            __nv_bfloat16* dAl = smem + (nxt * 4 + 1) * TILE_ELE;
            __nv_bfloat16* dBh = smem + (nxt * 4 + 2) * TILE_ELE;
            __nv_bfloat16* dBl = smem + (nxt * 4 + 3) * TILE_ELE;
#pragma unroll
            for (int i = 0; i < 4; i++) {
                float4 v = st.a[i];
                __nv_bfloat16 h0 = __float2bfloat16(v.x), h1 = __float2bfloat16(v.y);
                __nv_bfloat16 h2 = __float2bfloat16(v.z), h3 = __float2bfloat16(v.w);
                __nv_bfloat16 l0 = __float2bfloat16(v.x - __bfloat162float(h0));
                __nv_bfloat16 l1 = __float2bfloat16(v.y - __bfloat162float(h1));
                __nv_bfloat16 l2 = __float2bfloat16(v.z - __bfloat162float(h2));
                __nv_bfloat16 l3 = __float2bfloat16(v.w - __bfloat162float(h3));
                *(__nv_bfloat162*)(dAh + stsOff + i * 4)     = __halves2bfloat162(h0, h1);
                *(__nv_bfloat162*)(dAh + stsOff + i * 4 + 2) = __halves2bfloat162(h2, h3);
                *(__nv_bfloat162*)(dAl + stsOff + i * 4)     = __halves2bfloat162(l0, l1);
                *(__nv_bfloat162*)(dAl + stsOff + i * 4 + 2) = __halves2bfloat162(l2, l3);
            }
            *(uint4*)(dBh + stsOff)     = st.bh[0];
            *(uint4*)(dBh + stsOff + 8) = st.bh[1];
            *(uint4*)(dBl + stsOff)     = st.bl[0];
            *(uint4*)(dBl + stsOff + 8) = st.bl[1];
        }
        __syncthreads();
    }

    // ---- epilogue ----
#pragma unroll
    for (int mb = 0; mb < 4; mb++) {
        const int r = mBase + wm * 64 + mb * 16 + (lane >> 2);
#pragma unroll
        for (int nb = 0; nb < 4; nb++) {
            const int ccol = nBase + wn * 32 + nb * 8 + (lane & 3) * 2;
            float2 v0 = make_float2(acc[mb][nb][0], acc[mb][nb][1]);
            float2 v1 = make_float2(acc[mb][nb][2], acc[mb][nb][3]);
            *(float2*)&Cz[(long)r * ldc + ccol] = v0;
            *(float2*)&Cz[(long)(r + 8) * ldc + ccol] = v1;
        }
    }
}

// ---------------- flash attention (fp32, causal + ALiBi) ---------------------
#define QT_STRIDE 65
#define VS_STRIDE 132
#define PS_STRIDE 68
#define SCALE_F 0.08838834764831845f   // 1/sqrt(128)

__global__ __launch_bounds__(256)
void flash_kernel(const float* __restrict__ Q, const float* __restrict__ Kb,
                  const float* __restrict__ Vb, float* __restrict__ AO)
{
    extern __shared__ float sm[];
    float* Qt = sm;                          // [128][65]  (k-major)
    float* Kt = Qt + 128 * QT_STRIDE;        // [128][65]  (k-major)
    float* Vs = Kt + 128 * QT_STRIDE;        // [64][132]  (row-major)
    float* Ps = Vs + 64 * VS_STRIDE;         // [64][68]

    const int qt = blockIdx.x;
    const int h  = blockIdx.y;
    const int b  = blockIdx.z;
    const int tid = threadIdx.x;
    const int tx = tid & 15;
    const int ty = tid >> 4;

    const int rowBase = b * 2048 + qt * 64;
    const float slope = exp2f(-0.5f * (float)(h + 1));

    {
        const int r  = tid >> 2;
        const int c0 = (tid & 3) * 32;
        const float* qp = Q + (long)(rowBase + r) * 2048 + h * 128 + c0;
#pragma unroll
        for (int u = 0; u < 8; u++) {
            float4 v = *(const float4*)(qp + u * 4);
            const int c = c0 + u * 4;
            Qt[(c + 0) * QT_STRIDE + r] = v.x;
            Qt[(c + 1) * QT_STRIDE + r] = v.y;
            Qt[(c + 2) * QT_STRIDE + r] = v.z;
            Qt[(c + 3) * QT_STRIDE + r] = v.w;
        }
    }

    float m[4], l[4], o[4][8];
#pragma unroll
    for (int i = 0; i < 4; i++) {
        m[i] = -1e30f; l[i] = 0.f;
#pragma unroll
        for (int c = 0; c < 8; c++) o[i][c] = 0.f;
    }

    const float* Kh = Kb + ((long)h * 4096 + b * 2048) * 128;
    const float* Vh = Vb + ((long)h * 4096 + b * 2048) * 128;

    __syncthreads();

    for (int jt = 0; jt <= qt; jt++) {
        {
            const int r  = tid >> 2;
            const int c0 = (tid & 3) * 32;
            const float* kp = Kh + (long)(jt * 64 + r) * 128 + c0;
            const float* vp = Vh + (long)(jt * 64 + r) * 128 + c0;
#pragma unroll
            for (int u = 0; u < 8; u++) {
                float4 kv = *(const float4*)(kp + u * 4);
                const int c = c0 + u * 4;
                Kt[(c + 0) * QT_STRIDE + r] = kv.x;
                Kt[(c + 1) * QT_STRIDE + r] = kv.y;
                Kt[(c + 2) * QT_STRIDE + r] = kv.z;
                Kt[(c + 3) * QT_STRIDE + r] = kv.w;
                float4 vv = *(const float4*)(vp + u * 4);
                *(float4*)&Vs[r * VS_STRIDE + c] = vv;
            }
        }
        __syncthreads();

        float s[4][4];
#pragma unroll
        for (int i = 0; i < 4; i++)
#pragma unroll
            for (int j = 0; j < 4; j++) s[i][j] = 0.f;

#pragma unroll 4
        for (int kk = 0; kk < 128; kk++) {
            float qv[4], kv[4];
#pragma unroll
            for (int i = 0; i < 4; i++) qv[i] = Qt[kk * QT_STRIDE + ty * 4 + i];
#pragma unroll
            for (int j = 0; j < 4; j++) kv[j] = Kt[kk * QT_STRIDE + tx + 16 * j];
#pragma unroll
            for (int i = 0; i < 4; i++)
#pragma unroll
                for (int j = 0; j < 4; j++) s[i][j] = fmaf(qv[i], kv[j], s[i][j]);
        }

#pragma unroll
        for (int i = 0; i < 4; i++) {
            const int grow = qt * 64 + ty * 4 + i;
#pragma unroll
            for (int j = 0; j < 4; j++) {
                const int gcol = jt * 64 + tx + 16 * j;
                if (gcol > grow) s[i][j] = -1e30f;
                else s[i][j] = s[i][j] * SCALE_F - slope * (float)(grow - gcol);
            }
        }

        float mn[4];
#pragma unroll
        for (int i = 0; i < 4; i++) {
            float v = fmaxf(fmaxf(s[i][0], s[i][1]), fmaxf(s[i][2], s[i][3]));
            v = fmaxf(v, __shfl_xor_sync(0xffffffffu, v, 1));
            v = fmaxf(v, __shfl_xor_sync(0xffffffffu, v, 2));
            v = fmaxf(v, __shfl_xor_sync(0xffffffffu, v, 4));
            v = fmaxf(v, __shfl_xor_sync(0xffffffffu, v, 8));
            mn[i] = v;
        }

#pragma unroll
        for (int i = 0; i < 4; i++) {
            const float mi = fmaxf(m[i], mn[i]);
            const float alpha = __expf(m[i] - mi);
            float acc = 0.f;
#pragma unroll
            for (int j = 0; j < 4; j++) {
                float p = __expf(s[i][j] - mi);
                acc += p;
                Ps[(ty * 4 + i) * PS_STRIDE + tx + 16 * j] = p;
            }
            acc += __shfl_xor_sync(0xffffffffu, acc, 1);
            acc += __shfl_xor_sync(0xffffffffu, acc, 2);
            acc += __shfl_xor_sync(0xffffffffu, acc, 4);
            acc += __shfl_xor_sync(0xffffffffu, acc, 8);
            l[i] = l[i] * alpha + acc;
            m[i] = mi;
#pragma unroll
            for (int c = 0; c < 8; c++) o[i][c] *= alpha;
        }
        __syncthreads();

#pragma unroll 2
        for (int kc = 0; kc < 64; kc++) {
            float pv[4], vv[8];
#pragma unroll
            for (int i = 0; i < 4; i++) pv[i] = Ps[(ty * 4 + i) * PS_STRIDE + kc];
#pragma unroll
            for (int c = 0; c < 8; c++) vv[c] = Vs[kc * VS_STRIDE + tx + 16 * c];
#pragma unroll
            for (int i = 0; i < 4; i++)
#pragma unroll
                for (int c = 0; c < 8; c++) o[i][c] = fmaf(pv[i], vv[c], o[i][c]);
        }
        __syncthreads();
    }

#pragma unroll
    for (int i = 0; i < 4; i++) {
        const float inv = 1.f / l[i];
        const long row = rowBase + ty * 4 + i;
#pragma unroll
        for (int c = 0; c < 8; c++)
            AO[row * 2048 + h * 128 + tx + 16 * c] = o[i][c] * inv;
    }
}

// ---------------- launch ------------------------------------------------------
extern "C" void kernel_launch(void* const* d_in, const int* in_sizes, int n_in,
                              void* d_out, int out_size)
{
    const float* X    = (const float*)d_in[0];  // [2,2048,2048]
    const float* Wqd  = (const float*)d_in[1];  // [1536,2048]
    const float* Wqu  = (const float*)d_in[2];  // [2048,1536]
    const float* Wkvd = (const float*)d_in[3];  // [512,2048]
    const float* kup  = (const float*)d_in[4];  // [16,512,128]
    const float* vup  = (const float*)d_in[5];  // [16,512,128]
    const float* Wo   = (const float*)d_in[6];  // [2048,2048]
    float* out = (float*)d_out;                 // [2,2048,2048]

    float *Xq, *Qb, *Cb, *Kb, *Vb, *AO;
    cudaGetSymbolAddress((void**)&Xq, g_Xq);
    cudaGetSymbolAddress((void**)&Qb, g_Qb);
    cudaGetSymbolAddress((void**)&Cb, g_Cb);
    cudaGetSymbolAddress((void**)&Kb, g_Kb);
    cudaGetSymbolAddress((void**)&Vb, g_Vb);
    cudaGetSymbolAddress((void**)&AO, g_AO);

    __nv_bfloat16 *wqdH, *wqdL, *wquH, *wquL, *wkvH, *wkvL, *woH, *woL;
    __nv_bfloat16 *kuH, *kuL, *vuH, *vuL;
    cudaGetSymbolAddress((void**)&wqdH, g_Wqd_hi); cudaGetSymbolAddress((void**)&wqdL, g_Wqd_lo);
    cudaGetSymbolAddress((void**)&wquH, g_Wqu_hi); cudaGetSymbolAddress((void**)&wquL, g_Wqu_lo);
    cudaGetSymbolAddress((void**)&wkvH, g_Wkvd_hi); cudaGetSymbolAddress((void**)&wkvL, g_Wkvd_lo);
    cudaGetSymbolAddress((void**)&woH, g_Wo_hi); cudaGetSymbolAddress((void**)&woL, g_Wo_lo);
    cudaGetSymbolAddress((void**)&kuH, g_kupT_hi); cudaGetSymbolAddress((void**)&kuL, g_kupT_lo);
    cudaGetSymbolAddress((void**)&vuH, g_vupT_hi); cudaGetSymbolAddress((void**)&vuL, g_vupT_lo);

    cudaFuncSetAttribute(gemm_tc, cudaFuncAttributeMaxDynamicSharedMemorySize, GEMM_SMEM);
    const size_t fsmem = (size_t)(128 * QT_STRIDE * 2 + 64 * VS_STRIDE + 64 * PS_STRIDE)
                        * sizeof(float);
    cudaFuncSetAttribute(flash_kernel, cudaFuncAttributeMaxDynamicSharedMemorySize,
                         (int)fsmem);

    // ---- weight prep ----
    conv_plain<<<(1536 * 2048 + 255) / 256, 256>>>(Wqd, wqdH, wqdL, 1536 * 2048);
    conv_plain<<<(2048 * 1536 + 255) / 256, 256>>>(Wqu, wquH, wquL, 2048 * 1536);
    conv_plain<<<(512 * 2048 + 255) / 256, 256>>>(Wkvd, wkvH, wkvL, 512 * 2048);
    conv_plain<<<(2048 * 2048 + 255) / 256, 256>>>(Wo, woH, woL, 2048 * 2048);
    conv_transpose<<<(16 * 512 * 128 + 255) / 256, 256>>>(kup, kuH, kuL, 16, 512, 128);
    conv_transpose<<<(16 * 512 * 128 + 255) / 256, 256>>>(vup, vuH, vuL, 16, 512, 128);

    // 1) Xq = X @ Wq_down^T              [4096,1536]
    gemm_tc<<<dim3(12, 32), 256, GEMM_SMEM>>>(X, wqdH, wqdL, Xq,
        4096, 1536, 2048, 2048, 1536, 0, 0);
    // 2) Q = Xq @ Wq_up^T                [4096,2048]
    gemm_tc<<<dim3(16, 32), 256, GEMM_SMEM>>>(Xq, wquH, wquL, Qb,
        4096, 2048, 1536, 1536, 2048, 0, 0);
    // 3) C = X @ Wkv_down^T              [4096,512]
    gemm_tc<<<dim3(4, 32), 256, GEMM_SMEM>>>(X, wkvH, wkvL, Cb,
        4096, 512, 2048, 2048, 512, 0, 0);
    // 4) K[h] = C @ k_up[h]              16 x [4096,128]
    gemm_tc<<<dim3(1, 32, 16), 256, GEMM_SMEM>>>(Cb, kuH, kuL, Kb,
        4096, 128, 512, 512, 128, (long)128 * 512, (long)4096 * 128);
    // 5) V[h] = C @ v_up[h]
    gemm_tc<<<dim3(1, 32, 16), 256, GEMM_SMEM>>>(Cb, vuH, vuL, Vb,
        4096, 128, 512, 512, 128, (long)128 * 512, (long)4096 * 128);
    // 6) attention
    flash_kernel<<<dim3(32, 16, 2), 256, fsmem>>>(Qb, Kb, Vb, AO);
    // 7) out = AO @ Wo^T                 [4096,2048]
    gemm_tc<<<dim3(16, 32), 256, GEMM_SMEM>>>(AO, woH, woL, out,
        4096, 2048, 2048, 2048, 2048, 0, 0);
}

// round 4
// speedup vs baseline: 2.6765x; 1.7045x over previous
#include <cuda_runtime.h>
#include <cuda_bf16.h>
#include <math.h>
#include <stdint.h>

// ---------------- scratch (device globals; no allocations allowed) -----------
__device__ float g_Xq[4096 * 1536];       // X @ Wq_down^T (fp32)
__device__ float g_Cb[4096 * 512];        // X @ Wkv_down^T (fp32)
__device__ float g_AO[4096 * 2048];       // attention output (fp32)

// bf16 hi/lo activation planes (produced by GEMM epilogues)
__device__ __nv_bfloat16 g_Qh[4096 * 2048], g_Ql[4096 * 2048];      // [row][h*128+d]
__device__ __nv_bfloat16 g_Kh[16 * 4096 * 128], g_Kl[16 * 4096 * 128]; // [h][row][d]
__device__ __nv_bfloat16 g_Vth[16 * 128 * 4096], g_Vtl[16 * 128 * 4096]; // [h][d][row]

// bf16 hi/lo weight planes ([N][K]; kup/vup transposed)
__device__ __nv_bfloat16 g_Wqd_hi[1536 * 2048], g_Wqd_lo[1536 * 2048];
__device__ __nv_bfloat16 g_Wqu_hi[2048 * 1536], g_Wqu_lo[2048 * 1536];
__device__ __nv_bfloat16 g_Wkvd_hi[512 * 2048], g_Wkvd_lo[512 * 2048];
__device__ __nv_bfloat16 g_Wo_hi[2048 * 2048], g_Wo_lo[2048 * 2048];
__device__ __nv_bfloat16 g_kupT_hi[16 * 128 * 512], g_kupT_lo[16 * 128 * 512];
__device__ __nv_bfloat16 g_vupT_hi[16 * 128 * 512], g_vupT_lo[16 * 128 * 512];

// ---------------- weight prep ------------------------------------------------
__global__ void conv_plain(const float* __restrict__ in, __nv_bfloat16* __restrict__ hi,
                           __nv_bfloat16* __restrict__ lo, int n)
{
    int i = blockIdx.x * blockDim.x + threadIdx.x;
    if (i >= n) return;
    float x = in[i];
    __nv_bfloat16 h = __float2bfloat16(x);
    hi[i] = h;
    lo[i] = __float2bfloat16(x - __bfloat162float(h));
}

// in: [Z][K][N] fp32 -> out planes [Z][N][K]
__global__ void conv_transpose(const float* __restrict__ in, __nv_bfloat16* __restrict__ hi,
                               __nv_bfloat16* __restrict__ lo, int Z, int K, int N)
{
    long i = (long)blockIdx.x * blockDim.x + threadIdx.x;
    long total = (long)Z * K * N;
    if (i >= total) return;
    int n = (int)(i % N);
    long t = i / N;
    int k = (int)(t % K);
    int z = (int)(t / K);
    float x = in[i];
    __nv_bfloat16 h = __float2bfloat16(x);
    long o = ((long)z * N + n) * K + k;
    hi[o] = h;
    lo[o] = __float2bfloat16(x - __bfloat162float(h));
}

// ---------------- shared helpers ---------------------------------------------
__device__ __forceinline__ uint32_t su(const void* p) {
    return (uint32_t)__cvta_generic_to_shared(p);
}
__device__ __forceinline__ void ldsm4(uint32_t* r, uint32_t addr) {
    asm volatile("ldmatrix.sync.aligned.m8n8.x4.shared.b16 {%0,%1,%2,%3}, [%4];"
                 : "=r"(r[0]), "=r"(r[1]), "=r"(r[2]), "=r"(r[3]) : "r"(addr));
}
__device__ __forceinline__ void mma16816(float* c, const uint32_t* a, const uint32_t* b) {
    asm volatile("mma.sync.aligned.m16n8k16.row.col.f32.bf16.bf16.f32 "
                 "{%0,%1,%2,%3}, {%4,%5,%6,%7}, {%8,%9}, {%0,%1,%2,%3};"
                 : "+f"(c[0]), "+f"(c[1]), "+f"(c[2]), "+f"(c[3])
                 : "r"(a[0]), "r"(a[1]), "r"(a[2]), "r"(a[3]), "r"(b[0]), "r"(b[1]));
}
__device__ __forceinline__ void cpa16(uint32_t dst, const void* src) {
    asm volatile("cp.async.cg.shared.global [%0], [%1], 16;" :: "r"(dst), "l"(src));
}
__device__ __forceinline__ uint32_t pack2(__nv_bfloat16 a, __nv_bfloat16 b) {
    __nv_bfloat162 t = __halves2bfloat162(a, b);
    return *(uint32_t*)&t;
}

// ---------------- bf16x3 tensor-core GEMM ------------------------------------
// C[M,N] = A[M,K] (fp32) @ B^T (B as bf16 hi/lo planes [N][K]).
// EPI: 0 = fp32 C; 1 = bf16 hi/lo planes row-major; 2 = bf16 hi/lo transposed [N][M]
#define BM 128
#define BN 128
#define BK 32
#define LDSS 40
#define TILE_ELE (128 * LDSS)
#define GEMM_SMEM (2 * 4 * TILE_ELE * 2)

struct StageRegs {
    float4 a[4];
    uint4 bh[2];
    uint4 bl[2];
};

template <int EPI>
__global__ __launch_bounds__(256)
void gemm_tc(const float* __restrict__ A,
             const __nv_bfloat16* __restrict__ Bhi,
             const __nv_bfloat16* __restrict__ Blo,
             float* __restrict__ C,
             __nv_bfloat16* __restrict__ Ohi,
             __nv_bfloat16* __restrict__ Olo,
             int M, int N, int K, int lda, int ldc,
             long bStrideZ, long cStrideZ)
{
    extern __shared__ __nv_bfloat16 smem[];

    const int tid = threadIdx.x;
    const int z = blockIdx.z;
    const int mBase = blockIdx.y * BM;
    const int nBase = blockIdx.x * BN;

    const __nv_bfloat16* BhiZ = Bhi + z * bStrideZ;
    const __nv_bfloat16* BloZ = Blo + z * bStrideZ;
    float* Cz = C + z * cStrideZ;
    __nv_bfloat16* OhiZ = Ohi + z * cStrideZ;
    __nv_bfloat16* OloZ = Olo + z * cStrideZ;

    const int ldRow = tid >> 1;
    const int ldCol = (tid & 1) * 16;
    const int stsOff = ldRow * LDSS + ldCol;

    const int lane = tid & 31;
    const int wid = tid >> 5;
    const int wm = wid >> 2;
    const int wn = wid & 3;
    const int aRowL = wm * 64 + (lane & 15);
    const int aKL = ((lane >> 4) << 3);
    const int bRowL = wn * 32 + ((lane >> 4) << 3) + (lane & 7);
    const int bKL = ((lane >> 3) & 1) << 3;

    const uint32_t smemBase = su(smem);
    const uint32_t planeBytes = TILE_ELE * 2;

    float acc[4][4][4];
#pragma unroll
    for (int i = 0; i < 4; i++)
#pragma unroll
        for (int j = 0; j < 4; j++)
#pragma unroll
            for (int k = 0; k < 4; k++) acc[i][j][k] = 0.f;

    StageRegs st;
    const int nt = K / BK;

    {
        const float* ap = A + (long)(mBase + ldRow) * lda + ldCol;
#pragma unroll
        for (int i = 0; i < 4; i++) st.a[i] = *(const float4*)(ap + i * 4);
        const __nv_bfloat16* bph = BhiZ + (long)(nBase + ldRow) * K + ldCol;
        const __nv_bfloat16* bpl = BloZ + (long)(nBase + ldRow) * K + ldCol;
        st.bh[0] = *(const uint4*)(bph); st.bh[1] = *(const uint4*)(bph + 8);
        st.bl[0] = *(const uint4*)(bpl); st.bl[1] = *(const uint4*)(bpl + 8);
    }
    {
        __nv_bfloat16* dAh = smem + 0 * TILE_ELE;
        __nv_bfloat16* dAl = smem + 1 * TILE_ELE;
        __nv_bfloat16* dBh = smem + 2 * TILE_ELE;
        __nv_bfloat16* dBl = smem + 3 * TILE_ELE;
#pragma unroll
        for (int i = 0; i < 4; i++) {
            float4 v = st.a[i];
            __nv_bfloat16 h0 = __float2bfloat16(v.x), h1 = __float2bfloat16(v.y);
            __nv_bfloat16 h2 = __float2bfloat16(v.z), h3 = __float2bfloat16(v.w);
            __nv_bfloat16 l0 = __float2bfloat16(v.x - __bfloat162float(h0));
            __nv_bfloat16 l1 = __float2bfloat16(v.y - __bfloat162float(h1));
            __nv_bfloat16 l2 = __float2bfloat16(v.z - __bfloat162float(h2));
            __nv_bfloat16 l3 = __float2bfloat16(v.w - __bfloat162float(h3));
            *(__nv_bfloat162*)(dAh + stsOff + i * 4)     = __halves2bfloat162(h0, h1);
            *(__nv_bfloat162*)(dAh + stsOff + i * 4 + 2) = __halves2bfloat162(h2, h3);
            *(__nv_bfloat162*)(dAl + stsOff + i * 4)     = __halves2bfloat162(l0, l1);
            *(__nv_bfloat162*)(dAl + stsOff + i * 4 + 2) = __halves2bfloat162(l2, l3);
        }
        *(uint4*)(dBh + stsOff)     = st.bh[0];
        *(uint4*)(dBh + stsOff + 8) = st.bh[1];
        *(uint4*)(dBl + stsOff)     = st.bl[0];
        *(uint4*)(dBl + stsOff + 8) = st.bl[1];
    }
    __syncthreads();

    for (int kt = 0; kt < nt; kt++) {
        const int cur = kt & 1;
        const bool more = (kt + 1 < nt);

        if (more) {
            const float* ap = A + (long)(mBase + ldRow) * lda + (kt + 1) * BK + ldCol;
#pragma unroll
            for (int i = 0; i < 4; i++) st.a[i] = *(const float4*)(ap + i * 4);
            const __nv_bfloat16* bph = BhiZ + (long)(nBase + ldRow) * K + (kt + 1) * BK + ldCol;
            const __nv_bfloat16* bpl = BloZ + (long)(nBase + ldRow) * K + (kt + 1) * BK + ldCol;
            st.bh[0] = *(const uint4*)(bph); st.bh[1] = *(const uint4*)(bph + 8);
            st.bl[0] = *(const uint4*)(bpl); st.bl[1] = *(const uint4*)(bpl + 8);
        }

        const uint32_t sAh = smemBase + (cur * 4 + 0) * planeBytes;
        const uint32_t sAl = smemBase + (cur * 4 + 1) * planeBytes;
        const uint32_t sBh = smemBase + (cur * 4 + 2) * planeBytes;
        const uint32_t sBl = smemBase + (cur * 4 + 3) * planeBytes;

#pragma unroll
        for (int ks = 0; ks < BK; ks += 16) {
            uint32_t Ah[4][4], Al[4][4];
#pragma unroll
            for (int mb = 0; mb < 4; mb++) {
                const uint32_t off = ((aRowL + mb * 16) * LDSS + aKL + ks) * 2;
                ldsm4(Ah[mb], sAh + off);
                ldsm4(Al[mb], sAl + off);
            }
            uint32_t Bh[4][2], Bl[4][2];
#pragma unroll
            for (int nb2 = 0; nb2 < 2; nb2++) {
                const uint32_t off = ((bRowL + nb2 * 16) * LDSS + bKL + ks) * 2;
                uint32_t r[4];
                ldsm4(r, sBh + off);
                Bh[nb2 * 2][0] = r[0]; Bh[nb2 * 2][1] = r[1];
                Bh[nb2 * 2 + 1][0] = r[2]; Bh[nb2 * 2 + 1][1] = r[3];
                ldsm4(r, sBl + off);
                Bl[nb2 * 2][0] = r[0]; Bl[nb2 * 2][1] = r[1];
                Bl[nb2 * 2 + 1][0] = r[2]; Bl[nb2 * 2 + 1][1] = r[3];
            }
#pragma unroll
            for (int mb = 0; mb < 4; mb++)
#pragma unroll
                for (int nb = 0; nb < 4; nb++) {
                    mma16816(acc[mb][nb], Ah[mb], Bh[nb]);
                    mma16816(acc[mb][nb], Ah[mb], Bl[nb]);
                    mma16816(acc[mb][nb], Al[mb], Bh[nb]);
                }
        }

        if (more) {
            const int nxt = cur ^ 1;
            __nv_bfloat16* dAh = smem + (nxt * 4 + 0) * TILE_ELE;
            __nv_bfloat16* dAl = smem + (nxt * 4 + 1) * TILE_ELE;
            __nv_bfloat16* dBh = smem + (nxt * 4 + 2) * TILE_ELE;
            __nv_bfloat16* dBl = smem + (nxt * 4 + 3) * TILE_ELE;
#pragma unroll
            for (int i = 0; i < 4; i++) {
                float4 v = st.a[i];
                __nv_bfloat16 h0 = __float2bfloat16(v.x), h1 = __float2bfloat16(v.y);
                __nv_bfloat16 h2 = __float2bfloat16(v.z), h3 = __float2bfloat16(v.w);
                __nv_bfloat16 l0 = __float2bfloat16(v.x - __bfloat162float(h0));
                __nv_bfloat16 l1 = __float2bfloat16(v.y - __bfloat162float(h1));
                __nv_bfloat16 l2 = __float2bfloat16(v.z - __bfloat162float(h2));
                __nv_bfloat16 l3 = __float2bfloat16(v.w - __bfloat162float(h3));
                *(__nv_bfloat162*)(dAh + stsOff + i * 4)     = __halves2bfloat162(h0, h1);
                *(__nv_bfloat162*)(dAh + stsOff + i * 4 + 2) = __halves2bfloat162(h2, h3);
                *(__nv_bfloat162*)(dAl + stsOff + i * 4)     = __halves2bfloat162(l0, l1);
                *(__nv_bfloat162*)(dAl + stsOff + i * 4 + 2) = __halves2bfloat162(l2, l3);
            }
            *(uint4*)(dBh + stsOff)     = st.bh[0];
            *(uint4*)(dBh + stsOff + 8) = st.bh[1];
            *(uint4*)(dBl + stsOff)     = st.bl[0];
            *(uint4*)(dBl + stsOff + 8) = st.bl[1];
        }
        __syncthreads();
    }

    // ---- epilogue ----
#pragma unroll
    for (int mb = 0; mb < 4; mb++) {
        const int r = mBase + wm * 64 + mb * 16 + (lane >> 2);
#pragma unroll
        for (int nb = 0; nb < 4; nb++) {
            const int cc = nBase + wn * 32 + nb * 8 + (lane & 3) * 2;
            float v0 = acc[mb][nb][0], v1 = acc[mb][nb][1];
            float v2 = acc[mb][nb][2], v3 = acc[mb][nb][3];
            if (EPI == 0) {
                *(float2*)&Cz[(long)r * ldc + cc] = make_float2(v0, v1);
                *(float2*)&Cz[(long)(r + 8) * ldc + cc] = make_float2(v2, v3);
            } else {
                __nv_bfloat16 h0 = __float2bfloat16(v0), h1 = __float2bfloat16(v1);
                __nv_bfloat16 h2 = __float2bfloat16(v2), h3 = __float2bfloat16(v3);
                __nv_bfloat16 l0 = __float2bfloat16(v0 - __bfloat162float(h0));
                __nv_bfloat16 l1 = __float2bfloat16(v1 - __bfloat162float(h1));
                __nv_bfloat16 l2 = __float2bfloat16(v2 - __bfloat162float(h2));
                __nv_bfloat16 l3 = __float2bfloat16(v3 - __bfloat162float(h3));
                if (EPI == 1) {
                    *(__nv_bfloat162*)&OhiZ[(long)r * ldc + cc] = __halves2bfloat162(h0, h1);
                    *(__nv_bfloat162*)&OhiZ[(long)(r + 8) * ldc + cc] = __halves2bfloat162(h2, h3);
                    *(__nv_bfloat162*)&OloZ[(long)r * ldc + cc] = __halves2bfloat162(l0, l1);
                    *(__nv_bfloat162*)&OloZ[(long)(r + 8) * ldc + cc] = __halves2bfloat162(l2, l3);
                } else { // EPI == 2 : transposed [N][M]
                    OhiZ[(long)cc * ldc + r] = h0;
                    OhiZ[(long)(cc + 1) * ldc + r] = h1;
                    OhiZ[(long)cc * ldc + r + 8] = h2;
                    OhiZ[(long)(cc + 1) * ldc + r + 8] = h3;
                    OloZ[(long)cc * ldc + r] = l0;
                    OloZ[(long)(cc + 1) * ldc + r] = l1;
                    OloZ[(long)cc * ldc + r + 8] = l2;
                    OloZ[(long)(cc + 1) * ldc + r + 8] = l3;
                }
            }
        }
    }
}

// ---------------- tensor-core flash attention --------------------------------
// Br=128, Bc=64, d=128, 8 warps; bf16x3 for QK^T and PV; causal + ALiBi.
// Q planes [row][2048]; K planes [h][row][128]; Vt planes [h][d][row].
#define FQ_S 136               // smem row stride (17x16B -> conflict-free ldmatrix)
#define FV_S 72                // 9x16B
#define FQH_O 0
#define FQL_O 17408
#define FK_O 34816             // + stage*17408 ; hi +0, lo +8704
#define FV_O 69632             // + stage*18432 ; hi +0, lo +9216
#define FLASH_SMEM (106496 * 2)
#define SCALE_F 0.08838834764831845f

__global__ __launch_bounds__(256)
void flash_tc(const __nv_bfloat16* __restrict__ Qh, const __nv_bfloat16* __restrict__ Ql,
              const __nv_bfloat16* __restrict__ Kh, const __nv_bfloat16* __restrict__ Kl,
              const __nv_bfloat16* __restrict__ Vth, const __nv_bfloat16* __restrict__ Vtl,
              float* __restrict__ AO)
{
    extern __shared__ __nv_bfloat16 fsm[];
    const int qt = blockIdx.x, h = blockIdx.y, b = blockIdx.z;
    const int tid = threadIdx.x, lane = tid & 31, w = tid >> 5;
    const float slope = exp2f(-0.5f * (float)(h + 1));
    const int nt = 2 * qt + 2;

    const uint32_t fb = su(fsm);

    // ---- cp.async Q (group 0) ----
    {
        const int r = tid >> 1, cb = (tid & 1) * 64;
        const __nv_bfloat16* sh = Qh + (long)(b * 2048 + qt * 128 + r) * 2048 + h * 128 + cb;
        const __nv_bfloat16* sl = Ql + (long)(b * 2048 + qt * 128 + r) * 2048 + h * 128 + cb;
        const uint32_t dh = fb + (FQH_O + r * FQ_S + cb) * 2;
        const uint32_t dl = fb + (FQL_O + r * FQ_S + cb) * 2;
#pragma unroll
        for (int u = 0; u < 8; u++) { cpa16(dh + u * 16, sh + u * 8); cpa16(dl + u * 16, sl + u * 8); }
    }
    // ---- cp.async K/V stage loader ----
    auto loadKV = [&](int stg, int jt) {
        const int kr = tid >> 2, kcb = (tid & 3) * 32;
        const long krow = (long)h * 4096 + b * 2048 + jt * 64 + kr;
        const __nv_bfloat16* skh = Kh + krow * 128 + kcb;
        const __nv_bfloat16* skl = Kl + krow * 128 + kcb;
        const uint32_t kdh = fb + (FK_O + stg * 17408 + kr * FQ_S + kcb) * 2;
        const uint32_t kdl = kdh + 8704 * 2;
#pragma unroll
        for (int u = 0; u < 4; u++) { cpa16(kdh + u * 16, skh + u * 8); cpa16(kdl + u * 16, skl + u * 8); }
        const int vr = tid >> 1, vcb = (tid & 1) * 32;
        const long vrow = (long)h * 128 + vr;
        const __nv_bfloat16* svh = Vth + vrow * 4096 + b * 2048 + jt * 64 + vcb;
        const __nv_bfloat16* svl = Vtl + vrow * 4096 + b * 2048 + jt * 64 + vcb;
        const uint32_t vdh = fb + (FV_O + stg * 18432 + vr * FV_S + vcb) * 2;
        const uint32_t vdl = vdh + 9216 * 2;
#pragma unroll
        for (int u = 0; u < 4; u++) { cpa16(vdh + u * 16, svh + u * 8); cpa16(vdl + u * 16, svl + u * 8); }
    };
    loadKV(0, 0);
    asm volatile("cp.async.commit_group;");

    // ldmatrix address components
    const int aRow = w * 16 + (lane & 15);
    const int aCol8 = (lane >> 4) << 3;
    const int bRow8 = ((lane >> 4) << 3) + (lane & 7);
    const int bCol8 = ((lane >> 3) & 1) << 3;

    float m0 = -1e30f, m1 = -1e30f, l0 = 0.f, l1 = 0.f;
    float o[16][4];
#pragma unroll
    for (int i = 0; i < 16; i++)
#pragma unroll
        for (int j = 0; j < 4; j++) o[i][j] = 0.f;

    const int grow0 = qt * 128 + w * 16 + (lane >> 2);

    for (int jt = 0; jt < nt; jt++) {
        const int cur = jt & 1;
        if (jt > 0) __syncthreads();
        if (jt + 1 < nt) {
            loadKV(cur ^ 1, jt + 1);
            asm volatile("cp.async.commit_group;");
            asm volatile("cp.async.wait_group 1;");
        } else {
            asm volatile("cp.async.wait_group 0;");
        }
        __syncthreads();

        const uint32_t bKH = fb + (FK_O + cur * 17408) * 2;
        const uint32_t bKL = bKH + 8704 * 2;
        const uint32_t bVH = fb + (FV_O + cur * 18432) * 2;
        const uint32_t bVL = bVH + 9216 * 2;

        // ---- S = Q K^T ----
        float s[8][4];
#pragma unroll
        for (int i = 0; i < 8; i++)
#pragma unroll
            for (int j = 0; j < 4; j++) s[i][j] = 0.f;

#pragma unroll
        for (int ks = 0; ks < 8; ks++) {
            uint32_t qh[4], ql[4];
            const uint32_t aoff = (uint32_t)(aRow * FQ_S + ks * 16 + aCol8) * 2;
            ldsm4(qh, fb + FQH_O * 2 + aoff);
            ldsm4(ql, fb + FQL_O * 2 + aoff);
#pragma unroll
            for (int nb2 = 0; nb2 < 4; nb2++) {
                const uint32_t boff = (uint32_t)((nb2 * 16 + bRow8) * FQ_S + ks * 16 + bCol8) * 2;
                uint32_t kh[4], kl[4];
                ldsm4(kh, bKH + boff);
                ldsm4(kl, bKL + boff);
                mma16816(s[2 * nb2],     qh, &kh[0]);
                mma16816(s[2 * nb2],     qh, &kl[0]);
                mma16816(s[2 * nb2],     ql, &kh[0]);
                mma16816(s[2 * nb2 + 1], qh, &kh[2]);
                mma16816(s[2 * nb2 + 1], qh, &kl[2]);
                mma16816(s[2 * nb2 + 1], ql, &kh[2]);
            }
        }

        // ---- scale + ALiBi + causal ----
#pragma unroll
        for (int nb = 0; nb < 8; nb++) {
#pragma unroll
            for (int j = 0; j < 2; j++) {
                const int gc = jt * 64 + nb * 8 + (lane & 3) * 2 + j;
                float v = s[nb][j];
                s[nb][j] = (gc > grow0) ? -1e30f
                          : v * SCALE_F - slope * (float)(grow0 - gc);
                float v2 = s[nb][2 + j];
                s[nb][2 + j] = (gc > grow0 + 8) ? -1e30f
                          : v2 * SCALE_F - slope * (float)(grow0 + 8 - gc);
            }
        }

        // ---- online softmax ----
        float mx0 = -1e30f, mx1 = -1e30f;
#pragma unroll
        for (int nb = 0; nb < 8; nb++) {
            mx0 = fmaxf(mx0, fmaxf(s[nb][0], s[nb][1]));
            mx1 = fmaxf(mx1, fmaxf(s[nb][2], s[nb][3]));
        }
        mx0 = fmaxf(mx0, __shfl_xor_sync(0xffffffffu, mx0, 1));
        mx0 = fmaxf(mx0, __shfl_xor_sync(0xffffffffu, mx0, 2));
        mx1 = fmaxf(mx1, __shfl_xor_sync(0xffffffffu, mx1, 1));
        mx1 = fmaxf(mx1, __shfl_xor_sync(0xffffffffu, mx1, 2));
        const float mn0 = fmaxf(m0, mx0), mn1 = fmaxf(m1, mx1);
        const float al0 = __expf(m0 - mn0), al1 = __expf(m1 - mn1);
        m0 = mn0; m1 = mn1;

        float sum0 = 0.f, sum1 = 0.f;
#pragma unroll
        for (int nb = 0; nb < 8; nb++) {
            s[nb][0] = __expf(s[nb][0] - mn0); sum0 += s[nb][0];
            s[nb][1] = __expf(s[nb][1] - mn0); sum0 += s[nb][1];
            s[nb][2] = __expf(s[nb][2] - mn1); sum1 += s[nb][2];
            s[nb][3] = __expf(s[nb][3] - mn1); sum1 += s[nb][3];
        }
        sum0 += __shfl_xor_sync(0xffffffffu, sum0, 1);
        sum0 += __shfl_xor_sync(0xffffffffu, sum0, 2);
        sum1 += __shfl_xor_sync(0xffffffffu, sum1, 1);
        sum1 += __shfl_xor_sync(0xffffffffu, sum1, 2);
        l0 = l0 * al0 + sum0;
        l1 = l1 * al1 + sum1;

#pragma unroll
        for (int nb = 0; nb < 16; nb++) {
            o[nb][0] *= al0; o[nb][1] *= al0;
            o[nb][2] *= al1; o[nb][3] *= al1;
        }

        // ---- P fragments (hi/lo, in registers) ----
        uint32_t ph[4][4], pl[4][4];
#pragma unroll
        for (int kb = 0; kb < 4; kb++) {
#pragma unroll
            for (int q = 0; q < 4; q++) {
                const float x = s[2 * kb + (q >> 1)][(q & 1) * 2 + 0];
                const float y = s[2 * kb + (q >> 1)][(q & 1) * 2 + 1];
                const __nv_bfloat16 hx = __float2bfloat16(x), hy = __float2bfloat16(y);
                ph[kb][q] = pack2(hx, hy);
                pl[kb][q] = pack2(__float2bfloat16(x - __bfloat162float(hx)),
                                  __float2bfloat16(y - __bfloat162float(hy)));
            }
        }

        // ---- O += P V ----
#pragma unroll
        for (int kb = 0; kb < 4; kb++) {
#pragma unroll
            for (int nb2 = 0; nb2 < 8; nb2++) {
                const uint32_t voff = (uint32_t)((nb2 * 16 + bRow8) * FV_S + kb * 16 + bCol8) * 2;
                uint32_t vh[4], vl[4];
                ldsm4(vh, bVH + voff);
                ldsm4(vl, bVL + voff);
                mma16816(o[2 * nb2],     ph[kb], &vh[0]);
                mma16816(o[2 * nb2],     ph[kb], &vl[0]);
                mma16816(o[2 * nb2],     pl[kb], &vh[0]);
                mma16816(o[2 * nb2 + 1], ph[kb], &vh[2]);
                mma16816(o[2 * nb2 + 1], ph[kb], &vl[2]);
                mma16816(o[2 * nb2 + 1], pl[kb], &vh[2]);
            }
        }
    }

    // ---- normalize + write ----
    const float inv0 = 1.f / l0, inv1 = 1.f / l1;
    const long row0 = (long)b * 2048 + qt * 128 + w * 16 + (lane >> 2);
#pragma unroll
    for (int nb = 0; nb < 16; nb++) {
        const int c = h * 128 + nb * 8 + (lane & 3) * 2;
        *(float2*)&AO[row0 * 2048 + c] = make_float2(o[nb][0] * inv0, o[nb][1] * inv0);
        *(float2*)&AO[(row0 + 8) * 2048 + c] = make_float2(o[nb][2] * inv1, o[nb][3] * inv1);
    }
}

// ---------------- launch ------------------------------------------------------
extern "C" void kernel_launch(void* const* d_in, const int* in_sizes, int n_in,
                              void* d_out, int out_size)
{
    const float* X    = (const float*)d_in[0];
    const float* Wqd  = (const float*)d_in[1];
    const float* Wqu  = (const float*)d_in[2];
    const float* Wkvd = (const float*)d_in[3];
    const float* kup  = (const float*)d_in[4];
    const float* vup  = (const float*)d_in[5];
    const float* Wo   = (const float*)d_in[6];
    float* out = (float*)d_out;

    float *Xq, *Cb, *AO;
    cudaGetSymbolAddress((void**)&Xq, g_Xq);
    cudaGetSymbolAddress((void**)&Cb, g_Cb);
    cudaGetSymbolAddress((void**)&AO, g_AO);

    __nv_bfloat16 *qH, *qL, *kH, *kL, *vtH, *vtL;
    cudaGetSymbolAddress((void**)&qH, g_Qh);  cudaGetSymbolAddress((void**)&qL, g_Ql);
    cudaGetSymbolAddress((void**)&kH, g_Kh);  cudaGetSymbolAddress((void**)&kL, g_Kl);
    cudaGetSymbolAddress((void**)&vtH, g_Vth); cudaGetSymbolAddress((void**)&vtL, g_Vtl);

    __nv_bfloat16 *wqdH, *wqdL, *wquH, *wquL, *wkvH, *wkvL, *woH, *woL;
    __nv_bfloat16 *kuH, *kuL, *vuH, *vuL;
    cudaGetSymbolAddress((void**)&wqdH, g_Wqd_hi); cudaGetSymbolAddress((void**)&wqdL, g_Wqd_lo);
    cudaGetSymbolAddress((void**)&wquH, g_Wqu_hi); cudaGetSymbolAddress((void**)&wquL, g_Wqu_lo);
    cudaGetSymbolAddress((void**)&wkvH, g_Wkvd_hi); cudaGetSymbolAddress((void**)&wkvL, g_Wkvd_lo);
    cudaGetSymbolAddress((void**)&woH, g_Wo_hi); cudaGetSymbolAddress((void**)&woL, g_Wo_lo);
    cudaGetSymbolAddress((void**)&kuH, g_kupT_hi); cudaGetSymbolAddress((void**)&kuL, g_kupT_lo);
    cudaGetSymbolAddress((void**)&vuH, g_vupT_hi); cudaGetSymbolAddress((void**)&vuL, g_vupT_lo);

    cudaFuncSetAttribute(gemm_tc<0>, cudaFuncAttributeMaxDynamicSharedMemorySize, GEMM_SMEM);
    cudaFuncSetAttribute(gemm_tc<1>, cudaFuncAttributeMaxDynamicSharedMemorySize, GEMM_SMEM);
    cudaFuncSetAttribute(gemm_tc<2>, cudaFuncAttributeMaxDynamicSharedMemorySize, GEMM_SMEM);
    cudaFuncSetAttribute(flash_tc, cudaFuncAttributeMaxDynamicSharedMemorySize, FLASH_SMEM);

    // ---- weight prep ----
    conv_plain<<<(1536 * 2048 + 255) / 256, 256>>>(Wqd, wqdH, wqdL, 1536 * 2048);
    conv_plain<<<(2048 * 1536 + 255) / 256, 256>>>(Wqu, wquH, wquL, 2048 * 1536);
    conv_plain<<<(512 * 2048 + 255) / 256, 256>>>(Wkvd, wkvH, wkvL, 512 * 2048);
    conv_plain<<<(2048 * 2048 + 255) / 256, 256>>>(Wo, woH, woL, 2048 * 2048);
    conv_transpose<<<(16 * 512 * 128 + 255) / 256, 256>>>(kup, kuH, kuL, 16, 512, 128);
    conv_transpose<<<(16 * 512 * 128 + 255) / 256, 256>>>(vup, vuH, vuL, 16, 512, 128);

    // 1) Xq = X @ Wq_down^T (fp32)
    gemm_tc<0><<<dim3(12, 32), 256, GEMM_SMEM>>>(X, wqdH, wqdL, Xq, nullptr, nullptr,
        4096, 1536, 2048, 2048, 1536, 0, 0);
    // 2) Q = Xq @ Wq_up^T -> bf16 hi/lo planes
    gemm_tc<1><<<dim3(16, 32), 256, GEMM_SMEM>>>(Xq, wquH, wquL, nullptr, qH, qL,
        4096, 2048, 1536, 1536, 2048, 0, 0);
    // 3) C = X @ Wkv_down^T (fp32)
    gemm_tc<0><<<dim3(4, 32), 256, GEMM_SMEM>>>(X, wkvH, wkvL, Cb, nullptr, nullptr,
        4096, 512, 2048, 2048, 512, 0, 0);
    // 4) K[h] = C @ k_up[h] -> bf16 hi/lo planes [h][row][d]
    gemm_tc<1><<<dim3(1, 32, 16), 256, GEMM_SMEM>>>(Cb, kuH, kuL, nullptr, kH, kL,
        4096, 128, 512, 512, 128, (long)128 * 512, (long)4096 * 128);
    // 5) V[h] = C @ v_up[h] -> bf16 hi/lo TRANSPOSED planes [h][d][row]
    gemm_tc<2><<<dim3(1, 32, 16), 256, GEMM_SMEM>>>(Cb, vuH, vuL, nullptr, vtH, vtL,
        4096, 128, 512, 512, 4096, (long)128 * 512, (long)128 * 4096);
    // 6) attention (tensor-core flash)
    flash_tc<<<dim3(16, 16, 2), 256, FLASH_SMEM>>>(qH, qL, kH, kL, vtH, vtL, AO);
    // 7) out = AO @ Wo^T (fp32)
    gemm_tc<0><<<dim3(16, 32), 256, GEMM_SMEM>>>(AO, woH, woL, out, nullptr, nullptr,
        4096, 2048, 2048, 2048, 2048, 0, 0);
}